// round 13
// baseline (speedup 1.0000x reference)
#include <cuda_runtime.h>
#include <cuda_bf16.h>
#include <cstdint>
#include <cstring>

#define BATCH 64
#define NI    2048
#define DI    16
#define NO    32
#define DOUT  16

#define KP    4
#define NPB   (NI / KP)     // 512 n per block
#define NPW   (NPB / 16)    // 32 n per warp

__device__ float g_wsum[NI * NO * DI];            // 4 MB  [n][o][i]
__device__ float g_c2[(size_t)NO * NI * BATCH];   // 16 MB [o][n][b]
__device__ float g_xt[(size_t)NI * BATCH * DI];   // 8 MB  [n][b][i]
__device__ float g_part[KP * BATCH * 512];        // [kp][b][o*16+d]

// ---------------------------------------------------------------------------
__device__ __forceinline__ unsigned ubf2(__nv_bfloat162 v) {
    unsigned r; memcpy(&r, &v, 4); return r;
}
__device__ __forceinline__ unsigned packh(__nv_bfloat16 lo, __nv_bfloat16 hi) {
    return ubf2(__halves2bfloat162(lo, hi));
}
__device__ __forceinline__ unsigned packf(float lo, float hi) {
    return ubf2(__floats2bfloat162_rn(lo, hi));
}
__device__ __forceinline__ void mma16(float* d,
                                      unsigned a0, unsigned a1, unsigned a2, unsigned a3,
                                      unsigned b0, unsigned b1) {
    asm volatile(
        "mma.sync.aligned.m16n8k16.row.col.f32.bf16.bf16.f32 "
        "{%0,%1,%2,%3}, {%4,%5,%6,%7}, {%8,%9}, {%0,%1,%2,%3};"
        : "+f"(d[0]), "+f"(d[1]), "+f"(d[2]), "+f"(d[3])
        : "r"(a0), "r"(a1), "r"(a2), "r"(a3), "r"(b0), "r"(b1));
}

// ============================================================================
// K0: Wsum[n][o][i] = sum_d W[n][o][d][i].  Warp = 2 rows, 16-lane contiguous
// 256B reads (nL=4), d-reduce via shfl_xor(4,8).  grid 4096 x 256.
// ============================================================================
__global__ void __launch_bounds__(256)
caps_wsum(const float* __restrict__ Wg) {
    const int t    = threadIdx.x;
    const int lane = t & 31;
    const int row  = blockIdx.x * 16 + (t >> 4);   // no-row 0..65535
    const int f0   = t & 15;                       // float4 idx within 256B

    const float4* src = (const float4*)(Wg + (size_t)row * 256);
    float4 s = make_float4(0.f, 0.f, 0.f, 0.f);
#pragma unroll
    for (int k = 0; k < 4; k++) {
        float4 v = __ldg(src + f0 + 16 * k);       // d = (f0>>2)+4k, iq = f0&3
        s.x += v.x; s.y += v.y; s.z += v.z; s.w += v.w;
    }
    // reduce over d0 = (f0>>2)&3 : lanes differing in bits 2,3
#pragma unroll
    for (int m = 4; m <= 8; m <<= 1) {
        s.x += __shfl_xor_sync(0xffffffffu, s.x, m);
        s.y += __shfl_xor_sync(0xffffffffu, s.y, m);
        s.z += __shfl_xor_sync(0xffffffffu, s.z, m);
        s.w += __shfl_xor_sync(0xffffffffu, s.w, m);
    }
    if ((f0 >> 2) == 0)    // lanes f0 = 0..3 hold iq = f0
        *(float4*)(g_wsum + (size_t)row * 16 + f0 * 4) = s;
    (void)lane;
}

// ============================================================================
// K1: routing from Wsum + x transpose.  grid 1024, block 128, lane = b.
// ============================================================================
__global__ void __launch_bounds__(128)
caps_route2(const float* __restrict__ inp) {
    __shared__ float ws[2][512];
    const int t  = threadIdx.x;
    const int n2 = blockIdx.x;

#pragma unroll
    for (int k = 0; k < 2; k++) {
        const int f   = t + k * 128;
        const int nn2 = f >> 7;
        const int rem = f & 127;
        *(float4*)(&ws[nn2][rem * 4]) =
            *(const float4*)(g_wsum + ((size_t)(2 * n2 + nn2)) * 512 + rem * 4);
    }
    __syncthreads();

    const int wid  = t >> 5;
    const int lane = t & 31;
    const int nn   = wid >> 1;
    const int bh   = wid & 1;
    const int n    = 2 * n2 + nn;
    const int b    = bh * 32 + lane;

    const float4* xr = (const float4*)(inp + ((size_t)b * NI + n) * 16);
    const float4 x0 = __ldg(xr + 0), x1 = __ldg(xr + 1);
    const float4 x2 = __ldg(xr + 2), x3 = __ldg(xr + 3);

    // ---- transposed x for the contraction kernel ----
    {
        float4* xtp = (float4*)(g_xt + ((size_t)n * BATCH + b) * 16);
        xtp[0] = x0; xtp[1] = x1; xtp[2] = x2; xtp[3] = x3;
    }

    float h[32];
#pragma unroll
    for (int o = 0; o < 32; o++) {
        const float4* wr = (const float4*)(&ws[nn][o * 16]);
        float4 w0 = wr[0], w1 = wr[1], w2 = wr[2], w3 = wr[3];
        float hv = w0.x * x0.x;
        hv = fmaf(w0.y, x0.y, hv); hv = fmaf(w0.z, x0.z, hv); hv = fmaf(w0.w, x0.w, hv);
        hv = fmaf(w1.x, x1.x, hv); hv = fmaf(w1.y, x1.y, hv); hv = fmaf(w1.z, x1.z, hv); hv = fmaf(w1.w, x1.w, hv);
        hv = fmaf(w2.x, x2.x, hv); hv = fmaf(w2.y, x2.y, hv); hv = fmaf(w2.z, x2.z, hv); hv = fmaf(w2.w, x2.w, hv);
        hv = fmaf(w3.x, x3.x, hv); hv = fmaf(w3.y, x3.y, hv); hv = fmaf(w3.z, x3.z, hv); hv = fmaf(w3.w, x3.w, hv);
        h[o] = hv;
    }

    float e1[32], s1 = 0.f;
#pragma unroll
    for (int o = 0; o < 32; o++) {
        e1[o] = __expf(h[o] * 0.03125f);
        s1 += e1[o];
    }
    const float inv1 = __fdividef(1.f, s1);
    float e2[32], s2 = 0.f;
#pragma unroll
    for (int o = 0; o < 32; o++) {
        const float b1 = h[o] * 0.03125f;
        const float b2 = fmaf(e1[o] * inv1, h[o], b1);
        e2[o] = __expf(b2);
        s2 += e2[o];
    }
    const float inv2 = __fdividef(1.f, s2);

#pragma unroll
    for (int o = 0; o < 32; o++)
        g_c2[((size_t)o * NI + n) * BATCH + b] = e2[o] * inv2;
}

// ============================================================================
// K3: mma.sync bf16 m16n8k16 contraction (split-bf16, 3 terms).
//   grid (4 kp, 32 o), 512 threads = 16 warps.  Warp w: n = n0 + w + 16*j.
//   x fragments from g_xt[n][b][i] -> 512B-contiguous per LDG (nL=4).
// ============================================================================
#define SRED_STR 1032
#define SMEMC_BYTES (16 * SRED_STR * 4)   // 66048

__global__ __launch_bounds__(512, 1)
void caps_contract(const float* __restrict__ inp, const float* __restrict__ Wg) {
    extern __shared__ float sred[];
    const int t    = threadIdx.x;
    const int w    = t >> 5;
    const int lane = t & 31;
    const int r    = lane >> 2;
    const int c    = lane & 3;
    const int kp   = blockIdx.x;
    const int o    = blockIdx.y;
    const int n0   = kp * NPB;

    float acc[4][2][4];
#pragma unroll
    for (int mt = 0; mt < 4; mt++)
#pragma unroll
        for (int dt = 0; dt < 2; dt++)
#pragma unroll
            for (int q = 0; q < 4; q++) acc[mt][dt][q] = 0.f;

    const float* xtb = g_xt + (size_t)r * DI + 4 * c;            // + (n*64 + b0)*16
    const float* c2p = g_c2 + (size_t)o * (NI * BATCH) + r;
    const float* wbp = Wg + (size_t)o * 256 + r * 16 + c * 4;

    for (int j = 0; j < NPW; j++) {
        const int n = n0 + w + j * 16;
        const float* c2n = c2p + (size_t)n * BATCH;
        const float* xn  = xtb + (size_t)n * (BATCH * DI);

        // ---- hoisted loads: 2 W + 8 x + 8 c2 ----
        float4 wv[2];
        wv[0] = __ldg((const float4*)(wbp + (size_t)n * 8192));
        wv[1] = __ldg((const float4*)(wbp + (size_t)n * 8192 + 128));
        float4 xv[8];
        float  cva[8];
#pragma unroll
        for (int mt = 0; mt < 4; mt++) {
            cva[2 * mt]     = __ldg(c2n + mt * 16);
            cva[2 * mt + 1] = __ldg(c2n + mt * 16 + 8);
            xv[2 * mt]      = __ldg((const float4*)(xn + (size_t)(mt * 16) * DI));
            xv[2 * mt + 1]  = __ldg((const float4*)(xn + (size_t)(mt * 16 + 8) * DI));
        }

        // ---- B fragments: hi/lo bf16 ----
        unsigned bhx[2][2], blx[2][2];
#pragma unroll
        for (int dt = 0; dt < 2; dt++) {
            const float4 v = wv[dt];
            __nv_bfloat16 hx = __float2bfloat16(v.x), hy = __float2bfloat16(v.y);
            __nv_bfloat16 hz = __float2bfloat16(v.z), hw = __float2bfloat16(v.w);
            bhx[dt][0] = packh(hx, hy);
            bhx[dt][1] = packh(hz, hw);
            blx[dt][0] = packf(v.x - __bfloat162float(hx), v.y - __bfloat162float(hy));
            blx[dt][1] = packf(v.z - __bfloat162float(hz), v.w - __bfloat162float(hw));
        }

#pragma unroll
        for (int mt = 0; mt < 4; mt++) {
            const float c2a = cva[2 * mt];
            const float c2b = cva[2 * mt + 1];
            const float4 xa = xv[2 * mt];
            const float4 xz = xv[2 * mt + 1];
            const float y0 = c2a * xa.x, y1 = c2a * xa.y, y2 = c2a * xa.z, y3 = c2a * xa.w;
            const float z0 = c2b * xz.x, z1 = c2b * xz.y, z2 = c2b * xz.z, z3 = c2b * xz.w;

            __nv_bfloat16 hy0 = __float2bfloat16(y0), hy1 = __float2bfloat16(y1);
            __nv_bfloat16 hy2 = __float2bfloat16(y2), hy3 = __float2bfloat16(y3);
            __nv_bfloat16 hz0 = __float2bfloat16(z0), hz1 = __float2bfloat16(z1);
            __nv_bfloat16 hz2 = __float2bfloat16(z2), hz3 = __float2bfloat16(z3);

            const unsigned aH0 = packh(hy0, hy1);
            const unsigned aH1 = packh(hz0, hz1);
            const unsigned aH2 = packh(hy2, hy3);
            const unsigned aH3 = packh(hz2, hz3);
            const unsigned aL0 = packf(y0 - __bfloat162float(hy0), y1 - __bfloat162float(hy1));
            const unsigned aL1 = packf(z0 - __bfloat162float(hz0), z1 - __bfloat162float(hz1));
            const unsigned aL2 = packf(y2 - __bfloat162float(hy2), y3 - __bfloat162float(hy3));
            const unsigned aL3 = packf(z2 - __bfloat162float(hz2), z3 - __bfloat162float(hz3));

#pragma unroll
            for (int dt = 0; dt < 2; dt++) {
                mma16(acc[mt][dt], aH0, aH1, aH2, aH3, bhx[dt][0], bhx[dt][1]);
                mma16(acc[mt][dt], aH0, aH1, aH2, aH3, blx[dt][0], blx[dt][1]);
                mma16(acc[mt][dt], aL0, aL1, aL2, aL3, bhx[dt][0], bhx[dt][1]);
            }
        }
    }

    // ---- epilogue: per-warp partial -> smem, cross-warp reduce -------------
#pragma unroll
    for (int mt = 0; mt < 4; mt++)
#pragma unroll
        for (int dt = 0; dt < 2; dt++) {
            const int base0 = w * SRED_STR + (mt * 16 + r) * 16 + dt * 8 + 2 * c;
            *(float2*)(sred + base0)       = make_float2(acc[mt][dt][0], acc[mt][dt][1]);
            *(float2*)(sred + base0 + 128) = make_float2(acc[mt][dt][2], acc[mt][dt][3]);
        }
    __syncthreads();

#pragma unroll
    for (int rep = 0; rep < 2; rep++) {
        const int v = t + rep * 512;
        float s = 0.f;
#pragma unroll
        for (int k = 0; k < 16; k++) s += sred[k * SRED_STR + v];
        const int b = v >> 4;
        const int d = v & 15;
        g_part[(kp * BATCH + b) * 512 + o * 16 + d] = s;
    }
}

// ============================================================================
// Finalize: sum 4 kp partials + squash.  grid (64 b, 2 oh), 256 threads.
// ============================================================================
__global__ void __launch_bounds__(256)
caps_fin(float* __restrict__ out) {
    __shared__ float q[256];
    const int b  = blockIdx.x;
    const int od = blockIdx.y * 256 + threadIdx.x;
    const int t  = threadIdx.x;
    float s = 0.f;
#pragma unroll
    for (int kp = 0; kp < KP; kp++) s += g_part[(kp * BATCH + b) * 512 + od];
    q[t] = s * s;
    __syncthreads();
    const int ol = t >> 4;
    float s2 = 0.f;
#pragma unroll
    for (int k = 0; k < 16; k++) s2 += q[ol * 16 + k];
    const float scale = s2 / ((1.f + s2) * sqrtf(s2 + 1e-7f));
    out[(size_t)b * 512 + od] = scale * s;
}

// ============================================================================
extern "C" void kernel_launch(void* const* d_in, const int* in_sizes, int n_in,
                              void* d_out, int out_size) {
    const float* inp;
    const float* Wg;
    if (in_sizes[0] == BATCH * NI * DI) {
        inp = (const float*)d_in[0];
        Wg  = (const float*)d_in[1];
    } else {
        inp = (const float*)d_in[1];
        Wg  = (const float*)d_in[0];
    }

    cudaFuncSetAttribute(caps_contract, cudaFuncAttributeMaxDynamicSharedMemorySize,
                         SMEMC_BYTES);

    caps_wsum<<<4096, 256>>>(Wg);
    caps_route2<<<NI / 2, 128>>>(inp);
    caps_contract<<<dim3(KP, NO), 512, SMEMC_BYTES>>>(inp, Wg);
    caps_fin<<<dim3(BATCH, 2), 256>>>((float*)d_out);
}

// round 15
// speedup vs baseline: 1.2376x; 1.2376x over previous
#include <cuda_runtime.h>
#include <cuda_fp16.h>
#include <cstdint>
#include <cstring>

#define BATCH 64
#define NI    2048
#define DI    16
#define NO    32
#define DOUT  16

#define KP    4
#define NPB   (NI / KP)     // 512 n per block
#define NPW   (NPB / 16)    // 32 n per warp

__device__ float g_wsum[NI * NO * DI];            // 4 MB  [n][o][i]
__device__ float g_c2[(size_t)NO * NI * BATCH];   // 16 MB [o][n][b]
__device__ float g_xt[(size_t)NI * BATCH * DI];   // 8 MB  [n][b][i]
__device__ float g_part[KP * BATCH * 512];        // [kp][b][o*16+d]

// ---------------------------------------------------------------------------
__device__ __forceinline__ unsigned uh2(__half2 v) {
    unsigned r; memcpy(&r, &v, 4); return r;
}
// pack two floats -> half2 (lo = first k-slot)  [one F2FP.PACK instr]
__device__ __forceinline__ unsigned packh2f(float lo, float hi) {
    return uh2(__floats2half2_rn(lo, hi));
}
__device__ __forceinline__ void mma16h(float* d,
                                       unsigned a0, unsigned a1, unsigned a2, unsigned a3,
                                       unsigned b0, unsigned b1) {
    asm volatile(
        "mma.sync.aligned.m16n8k16.row.col.f32.f16.f16.f32 "
        "{%0,%1,%2,%3}, {%4,%5,%6,%7}, {%8,%9}, {%0,%1,%2,%3};"
        : "+f"(d[0]), "+f"(d[1]), "+f"(d[2]), "+f"(d[3])
        : "r"(a0), "r"(a1), "r"(a2), "r"(a3), "r"(b0), "r"(b1));
}

// ============================================================================
// K0: Wsum[n][o][i] = sum_d W[n][o][d][i].  Warp = 2 rows, 16-lane contiguous
// 256B reads, d-reduce via shfl_xor.  grid 4096 x 256.
// ============================================================================
__global__ void __launch_bounds__(256)
caps_wsum(const float* __restrict__ Wg) {
    const int t   = threadIdx.x;
    const int row = blockIdx.x * 16 + (t >> 4);
    const int f0  = t & 15;

    const float4* src = (const float4*)(Wg + (size_t)row * 256);
    float4 s = make_float4(0.f, 0.f, 0.f, 0.f);
#pragma unroll
    for (int k = 0; k < 4; k++) {
        float4 v = __ldg(src + f0 + 16 * k);
        s.x += v.x; s.y += v.y; s.z += v.z; s.w += v.w;
    }
#pragma unroll
    for (int m = 4; m <= 8; m <<= 1) {
        s.x += __shfl_xor_sync(0xffffffffu, s.x, m);
        s.y += __shfl_xor_sync(0xffffffffu, s.y, m);
        s.z += __shfl_xor_sync(0xffffffffu, s.z, m);
        s.w += __shfl_xor_sync(0xffffffffu, s.w, m);
    }
    if ((f0 >> 2) == 0)
        *(float4*)(g_wsum + (size_t)row * 16 + f0 * 4) = s;
}

// ============================================================================
// K1: routing from Wsum + x transpose.  grid 1024, block 128, lane = b.
// ============================================================================
__global__ void __launch_bounds__(128)
caps_route2(const float* __restrict__ inp) {
    __shared__ float ws[2][512];
    const int t  = threadIdx.x;
    const int n2 = blockIdx.x;

#pragma unroll
    for (int k = 0; k < 2; k++) {
        const int f   = t + k * 128;
        const int nn2 = f >> 7;
        const int rem = f & 127;
        *(float4*)(&ws[nn2][rem * 4]) =
            *(const float4*)(g_wsum + ((size_t)(2 * n2 + nn2)) * 512 + rem * 4);
    }
    __syncthreads();

    const int wid  = t >> 5;
    const int lane = t & 31;
    const int nn   = wid >> 1;
    const int bh   = wid & 1;
    const int n    = 2 * n2 + nn;
    const int b    = bh * 32 + lane;

    const float4* xr = (const float4*)(inp + ((size_t)b * NI + n) * 16);
    const float4 x0 = __ldg(xr + 0), x1 = __ldg(xr + 1);
    const float4 x2 = __ldg(xr + 2), x3 = __ldg(xr + 3);

    {
        float4* xtp = (float4*)(g_xt + ((size_t)n * BATCH + b) * 16);
        xtp[0] = x0; xtp[1] = x1; xtp[2] = x2; xtp[3] = x3;
    }

    float h[32];
#pragma unroll
    for (int o = 0; o < 32; o++) {
        const float4* wr = (const float4*)(&ws[nn][o * 16]);
        float4 w0 = wr[0], w1 = wr[1], w2 = wr[2], w3 = wr[3];
        float hv = w0.x * x0.x;
        hv = fmaf(w0.y, x0.y, hv); hv = fmaf(w0.z, x0.z, hv); hv = fmaf(w0.w, x0.w, hv);
        hv = fmaf(w1.x, x1.x, hv); hv = fmaf(w1.y, x1.y, hv); hv = fmaf(w1.z, x1.z, hv); hv = fmaf(w1.w, x1.w, hv);
        hv = fmaf(w2.x, x2.x, hv); hv = fmaf(w2.y, x2.y, hv); hv = fmaf(w2.z, x2.z, hv); hv = fmaf(w2.w, x2.w, hv);
        hv = fmaf(w3.x, x3.x, hv); hv = fmaf(w3.y, x3.y, hv); hv = fmaf(w3.z, x3.z, hv); hv = fmaf(w3.w, x3.w, hv);
        h[o] = hv;
    }

    float e1[32], s1 = 0.f;
#pragma unroll
    for (int o = 0; o < 32; o++) {
        e1[o] = __expf(h[o] * 0.03125f);
        s1 += e1[o];
    }
    const float inv1 = __fdividef(1.f, s1);
    float e2[32], s2 = 0.f;
#pragma unroll
    for (int o = 0; o < 32; o++) {
        const float b1 = h[o] * 0.03125f;
        const float b2 = fmaf(e1[o] * inv1, h[o], b1);
        e2[o] = __expf(b2);
        s2 += e2[o];
    }
    const float inv2 = __fdividef(1.f, s2);

#pragma unroll
    for (int o = 0; o < 32; o++)
        g_c2[((size_t)o * NI + n) * BATCH + b] = e2[o] * inv2;
}

// ============================================================================
// K3: mma.sync fp16 m16n8k16, 2-term split (aH*bH + aH*bL).
//   grid (4 kp, 32 o), 512 threads = 16 warps.  Warp w: n = n0 + w + 16*j.
//   A = fp16(c2*x) (hi only); B = W split hi/lo fp16.
//   Dropped term aL*bH: rel err ~1e-4 after sqrt-K averaging (< 1e-3).
//   MMA/warp/n = 16 (vs 24 bf16-3term).
// ============================================================================
#define SRED_STR 1032
#define SMEMC_BYTES (16 * SRED_STR * 4)   // 66048

__global__ __launch_bounds__(512, 1)
void caps_contract(const float* __restrict__ inp, const float* __restrict__ Wg) {
    extern __shared__ float sred[];
    const int t    = threadIdx.x;
    const int w    = t >> 5;
    const int lane = t & 31;
    const int r    = lane >> 2;
    const int c    = lane & 3;
    const int kp   = blockIdx.x;
    const int o    = blockIdx.y;
    const int n0   = kp * NPB;

    float acc[4][2][4];
#pragma unroll
    for (int mt = 0; mt < 4; mt++)
#pragma unroll
        for (int dt = 0; dt < 2; dt++)
#pragma unroll
            for (int q = 0; q < 4; q++) acc[mt][dt][q] = 0.f;

    const float* xtb = g_xt + (size_t)r * DI + 4 * c;
    const float* c2p = g_c2 + (size_t)o * (NI * BATCH) + r;
    const float* wbp = Wg + (size_t)o * 256 + r * 16 + c * 4;

    for (int j = 0; j < NPW; j++) {
        const int n = n0 + w + j * 16;
        const float* c2n = c2p + (size_t)n * BATCH;
        const float* xn  = xtb + (size_t)n * (BATCH * DI);

        // ---- hoisted loads: 2 W + 8 x + 8 c2 ----
        float4 wv[2];
        wv[0] = __ldg((const float4*)(wbp + (size_t)n * 8192));
        wv[1] = __ldg((const float4*)(wbp + (size_t)n * 8192 + 128));
        float4 xv[8];
        float  cva[8];
#pragma unroll
        for (int mt = 0; mt < 4; mt++) {
            cva[2 * mt]     = __ldg(c2n + mt * 16);
            cva[2 * mt + 1] = __ldg(c2n + mt * 16 + 8);
            xv[2 * mt]      = __ldg((const float4*)(xn + (size_t)(mt * 16) * DI));
            xv[2 * mt + 1]  = __ldg((const float4*)(xn + (size_t)(mt * 16 + 8) * DI));
        }

        // ---- B fragments: fp16 hi/lo ----
        unsigned bhx[2][2], blx[2][2];
#pragma unroll
        for (int dt = 0; dt < 2; dt++) {
            const float4 v = wv[dt];
            const __half2 H0 = __floats2half2_rn(v.x, v.y);
            const __half2 H1 = __floats2half2_rn(v.z, v.w);
            const float2 F0 = __half22float2(H0);
            const float2 F1 = __half22float2(H1);
            bhx[dt][0] = uh2(H0);
            bhx[dt][1] = uh2(H1);
            blx[dt][0] = packh2f(v.x - F0.x, v.y - F0.y);
            blx[dt][1] = packh2f(v.z - F1.x, v.w - F1.y);
        }

#pragma unroll
        for (int mt = 0; mt < 4; mt++) {
            const float c2a = cva[2 * mt];
            const float c2b = cva[2 * mt + 1];
            const float4 xa = xv[2 * mt];
            const float4 xz = xv[2 * mt + 1];
            // A hi only (2-term split): y = c2 * x, fp16
            const unsigned aH0 = packh2f(c2a * xa.x, c2a * xa.y);
            const unsigned aH1 = packh2f(c2b * xz.x, c2b * xz.y);
            const unsigned aH2 = packh2f(c2a * xa.z, c2a * xa.w);
            const unsigned aH3 = packh2f(c2b * xz.z, c2b * xz.w);

#pragma unroll
            for (int dt = 0; dt < 2; dt++) {
                mma16h(acc[mt][dt], aH0, aH1, aH2, aH3, bhx[dt][0], bhx[dt][1]);
                mma16h(acc[mt][dt], aH0, aH1, aH2, aH3, blx[dt][0], blx[dt][1]);
            }
        }
    }

    // ---- epilogue: per-warp partial -> smem, cross-warp reduce -------------
#pragma unroll
    for (int mt = 0; mt < 4; mt++)
#pragma unroll
        for (int dt = 0; dt < 2; dt++) {
            const int base0 = w * SRED_STR + (mt * 16 + r) * 16 + dt * 8 + 2 * c;
            *(float2*)(sred + base0)       = make_float2(acc[mt][dt][0], acc[mt][dt][1]);
            *(float2*)(sred + base0 + 128) = make_float2(acc[mt][dt][2], acc[mt][dt][3]);
        }
    __syncthreads();

#pragma unroll
    for (int rep = 0; rep < 2; rep++) {
        const int v = t + rep * 512;
        float s = 0.f;
#pragma unroll
        for (int k = 0; k < 16; k++) s += sred[k * SRED_STR + v];
        const int b = v >> 4;
        const int d = v & 15;
        g_part[(kp * BATCH + b) * 512 + o * 16 + d] = s;
    }
}

// ============================================================================
// Finalize: sum 4 kp partials + squash.  grid (64 b, 2 oh), 256 threads.
// ============================================================================
__global__ void __launch_bounds__(256)
caps_fin(float* __restrict__ out) {
    __shared__ float q[256];
    const int b  = blockIdx.x;
    const int od = blockIdx.y * 256 + threadIdx.x;
    const int t  = threadIdx.x;
    float s = 0.f;
#pragma unroll
    for (int kp = 0; kp < KP; kp++) s += g_part[(kp * BATCH + b) * 512 + od];
    q[t] = s * s;
    __syncthreads();
    const int ol = t >> 4;
    float s2 = 0.f;
#pragma unroll
    for (int k = 0; k < 16; k++) s2 += q[ol * 16 + k];
    const float scale = s2 / ((1.f + s2) * sqrtf(s2 + 1e-7f));
    out[(size_t)b * 512 + od] = scale * s;
}

// ============================================================================
extern "C" void kernel_launch(void* const* d_in, const int* in_sizes, int n_in,
                              void* d_out, int out_size) {
    const float* inp;
    const float* Wg;
    if (in_sizes[0] == BATCH * NI * DI) {
        inp = (const float*)d_in[0];
        Wg  = (const float*)d_in[1];
    } else {
        inp = (const float*)d_in[1];
        Wg  = (const float*)d_in[0];
    }

    cudaFuncSetAttribute(caps_contract, cudaFuncAttributeMaxDynamicSharedMemorySize,
                         SMEMC_BYTES);

    caps_wsum<<<4096, 256>>>(Wg);
    caps_route2<<<NI / 2, 128>>>(inp);
    caps_contract<<<dim3(KP, NO), 512, SMEMC_BYTES>>>(inp, Wg);
    caps_fin<<<dim3(BATCH, 2), 256>>>((float*)d_out);
}

// round 16
// speedup vs baseline: 1.4045x; 1.1348x over previous
#include <cuda_runtime.h>
#include <cuda_fp16.h>
#include <cstdint>
#include <cstring>

#define BATCH 64
#define NI    2048
#define DI    16
#define NO    32
#define DOUT  16

#define KP    4
#define NPB   (NI / KP)     // 512 n per block
#define NPW   (NPB / 16)    // 32 n per warp

__device__ float g_wsum[NI * NO * DI];            // 4 MB  [n][o][i]
__device__ float g_c2[(size_t)NO * NI * BATCH];   // 16 MB [o][n][b]
__device__ float g_xt[(size_t)NI * BATCH * DI];   // 8 MB  [n][b][i]
__device__ float g_part[KP * BATCH * 512];        // [kp][b][o*16+d]

// ---------------------------------------------------------------------------
__device__ __forceinline__ unsigned uh2(__half2 v) {
    unsigned r; memcpy(&r, &v, 4); return r;
}
__device__ __forceinline__ unsigned packh2f(float lo, float hi) {
    return uh2(__floats2half2_rn(lo, hi));
}
__device__ __forceinline__ void mma16h(float* d,
                                       unsigned a0, unsigned a1, unsigned a2, unsigned a3,
                                       unsigned b0, unsigned b1) {
    asm volatile(
        "mma.sync.aligned.m16n8k16.row.col.f32.f16.f16.f32 "
        "{%0,%1,%2,%3}, {%4,%5,%6,%7}, {%8,%9}, {%0,%1,%2,%3};"
        : "+f"(d[0]), "+f"(d[1]), "+f"(d[2]), "+f"(d[3])
        : "r"(a0), "r"(a1), "r"(a2), "r"(a3), "r"(b0), "r"(b1));
}

// ============================================================================
// K0: Wsum[n][o][i] = sum_d W[n][o][d][i].  Warp = 2 rows, 16-lane contiguous
// 256B reads, d-reduce via shfl_xor.  grid 4096 x 256.
// ============================================================================
__global__ void __launch_bounds__(256)
caps_wsum(const float* __restrict__ Wg) {
    const int t   = threadIdx.x;
    const int row = blockIdx.x * 16 + (t >> 4);
    const int f0  = t & 15;

    const float4* src = (const float4*)(Wg + (size_t)row * 256);
    float4 s = make_float4(0.f, 0.f, 0.f, 0.f);
#pragma unroll
    for (int k = 0; k < 4; k++) {
        float4 v = __ldg(src + f0 + 16 * k);
        s.x += v.x; s.y += v.y; s.z += v.z; s.w += v.w;
    }
#pragma unroll
    for (int m = 4; m <= 8; m <<= 1) {
        s.x += __shfl_xor_sync(0xffffffffu, s.x, m);
        s.y += __shfl_xor_sync(0xffffffffu, s.y, m);
        s.z += __shfl_xor_sync(0xffffffffu, s.z, m);
        s.w += __shfl_xor_sync(0xffffffffu, s.w, m);
    }
    if ((f0 >> 2) == 0)
        *(float4*)(g_wsum + (size_t)row * 16 + f0 * 4) = s;
}

// ============================================================================
// K1: routing from Wsum + x transpose.  grid 1024, block 128, lane = b.
// ============================================================================
__global__ void __launch_bounds__(128)
caps_route2(const float* __restrict__ inp) {
    __shared__ float ws[2][512];
    const int t  = threadIdx.x;
    const int n2 = blockIdx.x;

#pragma unroll
    for (int k = 0; k < 2; k++) {
        const int f   = t + k * 128;
        const int nn2 = f >> 7;
        const int rem = f & 127;
        *(float4*)(&ws[nn2][rem * 4]) =
            *(const float4*)(g_wsum + ((size_t)(2 * n2 + nn2)) * 512 + rem * 4);
    }
    __syncthreads();

    const int wid  = t >> 5;
    const int lane = t & 31;
    const int nn   = wid >> 1;
    const int bh   = wid & 1;
    const int n    = 2 * n2 + nn;
    const int b    = bh * 32 + lane;

    const float4* xr = (const float4*)(inp + ((size_t)b * NI + n) * 16);
    const float4 x0 = __ldg(xr + 0), x1 = __ldg(xr + 1);
    const float4 x2 = __ldg(xr + 2), x3 = __ldg(xr + 3);

    {
        float4* xtp = (float4*)(g_xt + ((size_t)n * BATCH + b) * 16);
        xtp[0] = x0; xtp[1] = x1; xtp[2] = x2; xtp[3] = x3;
    }

    float h[32];
#pragma unroll
    for (int o = 0; o < 32; o++) {
        const float4* wr = (const float4*)(&ws[nn][o * 16]);
        float4 w0 = wr[0], w1 = wr[1], w2 = wr[2], w3 = wr[3];
        float hv = w0.x * x0.x;
        hv = fmaf(w0.y, x0.y, hv); hv = fmaf(w0.z, x0.z, hv); hv = fmaf(w0.w, x0.w, hv);
        hv = fmaf(w1.x, x1.x, hv); hv = fmaf(w1.y, x1.y, hv); hv = fmaf(w1.z, x1.z, hv); hv = fmaf(w1.w, x1.w, hv);
        hv = fmaf(w2.x, x2.x, hv); hv = fmaf(w2.y, x2.y, hv); hv = fmaf(w2.z, x2.z, hv); hv = fmaf(w2.w, x2.w, hv);
        hv = fmaf(w3.x, x3.x, hv); hv = fmaf(w3.y, x3.y, hv); hv = fmaf(w3.z, x3.z, hv); hv = fmaf(w3.w, x3.w, hv);
        h[o] = hv;
    }

    float e1[32], s1 = 0.f;
#pragma unroll
    for (int o = 0; o < 32; o++) {
        e1[o] = __expf(h[o] * 0.03125f);
        s1 += e1[o];
    }
    const float inv1 = __fdividef(1.f, s1);
    float e2[32], s2 = 0.f;
#pragma unroll
    for (int o = 0; o < 32; o++) {
        const float b1 = h[o] * 0.03125f;
        const float b2 = fmaf(e1[o] * inv1, h[o], b1);
        e2[o] = __expf(b2);
        s2 += e2[o];
    }
    const float inv2 = __fdividef(1.f, s2);

#pragma unroll
    for (int o = 0; o < 32; o++)
        g_c2[((size_t)o * NI + n) * BATCH + b] = e2[o] * inv2;
}

// ============================================================================
// K3: mma.sync fp16 m16n8k16, single term (pure fp16 a and b).
//   grid (4 kp, 32 o), 512 threads = 16 warps.  Warp w: n = n0 + w + 16*j.
//   Error model (anchored by R15's measured 7e-5 for one dropped split term):
//   dropping both lo terms -> ~1-1.5e-4 total, 7x under threshold.
//   MMA/warp/n = 8.
// ============================================================================
#define SRED_STR 1032
#define SMEMC_BYTES (16 * SRED_STR * 4)   // 66048

__global__ __launch_bounds__(512, 1)
void caps_contract(const float* __restrict__ inp, const float* __restrict__ Wg) {
    extern __shared__ float sred[];
    const int t    = threadIdx.x;
    const int w    = t >> 5;
    const int lane = t & 31;
    const int r    = lane >> 2;
    const int c    = lane & 3;
    const int kp   = blockIdx.x;
    const int o    = blockIdx.y;
    const int n0   = kp * NPB;

    float acc[4][2][4];
#pragma unroll
    for (int mt = 0; mt < 4; mt++)
#pragma unroll
        for (int dt = 0; dt < 2; dt++)
#pragma unroll
            for (int q = 0; q < 4; q++) acc[mt][dt][q] = 0.f;

    const float* xtb = g_xt + (size_t)r * DI + 4 * c;
    const float* c2p = g_c2 + (size_t)o * (NI * BATCH) + r;
    const float* wbp = Wg + (size_t)o * 256 + r * 16 + c * 4;

    for (int j = 0; j < NPW; j++) {
        const int n = n0 + w + j * 16;
        const float* c2n = c2p + (size_t)n * BATCH;
        const float* xn  = xtb + (size_t)n * (BATCH * DI);

        // ---- hoisted loads: 2 W + 8 x + 8 c2 ----
        float4 wv[2];
        wv[0] = __ldg((const float4*)(wbp + (size_t)n * 8192));
        wv[1] = __ldg((const float4*)(wbp + (size_t)n * 8192 + 128));
        float4 xv[8];
        float  cva[8];
#pragma unroll
        for (int mt = 0; mt < 4; mt++) {
            cva[2 * mt]     = __ldg(c2n + mt * 16);
            cva[2 * mt + 1] = __ldg(c2n + mt * 16 + 8);
            xv[2 * mt]      = __ldg((const float4*)(xn + (size_t)(mt * 16) * DI));
            xv[2 * mt + 1]  = __ldg((const float4*)(xn + (size_t)(mt * 16 + 8) * DI));
        }

        // ---- B fragments: pure fp16 ----
        unsigned bhx[2][2];
#pragma unroll
        for (int dt = 0; dt < 2; dt++) {
            const float4 v = wv[dt];
            bhx[dt][0] = packh2f(v.x, v.y);
            bhx[dt][1] = packh2f(v.z, v.w);
        }

#pragma unroll
        for (int mt = 0; mt < 4; mt++) {
            const float c2a = cva[2 * mt];
            const float c2b = cva[2 * mt + 1];
            const float4 xa = xv[2 * mt];
            const float4 xz = xv[2 * mt + 1];
            const unsigned aH0 = packh2f(c2a * xa.x, c2a * xa.y);
            const unsigned aH1 = packh2f(c2b * xz.x, c2b * xz.y);
            const unsigned aH2 = packh2f(c2a * xa.z, c2a * xa.w);
            const unsigned aH3 = packh2f(c2b * xz.z, c2b * xz.w);

#pragma unroll
            for (int dt = 0; dt < 2; dt++)
                mma16h(acc[mt][dt], aH0, aH1, aH2, aH3, bhx[dt][0], bhx[dt][1]);
        }
    }

    // ---- epilogue: per-warp partial -> smem, cross-warp reduce -------------
#pragma unroll
    for (int mt = 0; mt < 4; mt++)
#pragma unroll
        for (int dt = 0; dt < 2; dt++) {
            const int base0 = w * SRED_STR + (mt * 16 + r) * 16 + dt * 8 + 2 * c;
            *(float2*)(sred + base0)       = make_float2(acc[mt][dt][0], acc[mt][dt][1]);
            *(float2*)(sred + base0 + 128) = make_float2(acc[mt][dt][2], acc[mt][dt][3]);
        }
    __syncthreads();

#pragma unroll
    for (int rep = 0; rep < 2; rep++) {
        const int v = t + rep * 512;
        float s = 0.f;
#pragma unroll
        for (int k = 0; k < 16; k++) s += sred[k * SRED_STR + v];
        const int b = v >> 4;
        const int d = v & 15;
        g_part[(kp * BATCH + b) * 512 + o * 16 + d] = s;
    }
}

// ============================================================================
// Finalize: sum 4 kp partials + squash.  grid (64 b, 2 oh), 256 threads.
// ============================================================================
__global__ void __launch_bounds__(256)
caps_fin(float* __restrict__ out) {
    __shared__ float q[256];
    const int b  = blockIdx.x;
    const int od = blockIdx.y * 256 + threadIdx.x;
    const int t  = threadIdx.x;
    float s = 0.f;
#pragma unroll
    for (int kp = 0; kp < KP; kp++) s += g_part[(kp * BATCH + b) * 512 + od];
    q[t] = s * s;
    __syncthreads();
    const int ol = t >> 4;
    float s2 = 0.f;
#pragma unroll
    for (int k = 0; k < 16; k++) s2 += q[ol * 16 + k];
    const float scale = s2 / ((1.f + s2) * sqrtf(s2 + 1e-7f));
    out[(size_t)b * 512 + od] = scale * s;
}

// ============================================================================
extern "C" void kernel_launch(void* const* d_in, const int* in_sizes, int n_in,
                              void* d_out, int out_size) {
    const float* inp;
    const float* Wg;
    if (in_sizes[0] == BATCH * NI * DI) {
        inp = (const float*)d_in[0];
        Wg  = (const float*)d_in[1];
    } else {
        inp = (const float*)d_in[1];
        Wg  = (const float*)d_in[0];
    }

    cudaFuncSetAttribute(caps_contract, cudaFuncAttributeMaxDynamicSharedMemorySize,
                         SMEMC_BYTES);

    caps_wsum<<<4096, 256>>>(Wg);
    caps_route2<<<NI / 2, 128>>>(inp);
    caps_contract<<<dim3(KP, NO), 512, SMEMC_BYTES>>>(inp, Wg);
    caps_fin<<<dim3(BATCH, 2), 256>>>((float*)d_out);
}